// round 15
// baseline (speedup 1.0000x reference)
#include <cuda_runtime.h>
#include <cuda_fp16.h>
#include <math.h>
#include <stdint.h>

#define BATCH 4
#define SEQ   2048
#define EMB   1024
#define NH    16
#define HD    64
#define MTOT  (BATCH*SEQ)   // 8192
#define KDIM  1024
#define KC    32            // GEMM K chunk
#define NKC   (KDIM/KC)     // 32 chunks

// ---------------- scratch (__device__ globals; allocation-free contract) ----
__device__ __half g_qh[(size_t)BATCH*NH*SEQ*HD];  // [bh][t][d], pre-scaled (hi only)
__device__ __half g_kh[(size_t)BATCH*NH*SEQ*HD];  // [bh][t][d]  (hi only)
__device__ __half g_vh[(size_t)BATCH*NH*HD*SEQ];  // [bh][d][t]  (hi only)
__device__ __half g_hs_hi[(size_t)MTOT*KDIM];
__device__ __half g_wq_hi[(size_t)3*EMB*KDIM];
__device__ __half g_wp_hi[(size_t)EMB*KDIM];
__device__ __half g_att_hi[(size_t)MTOT*EMB];

// ---------------- PTX helpers (baseline ISA only: sm_80-era) ----------------
__device__ __forceinline__ uint32_t smem_u32(const void* p) {
    uint32_t a;
    asm("{ .reg .u64 t; cvta.to.shared.u64 t, %1; cvt.u32.u64 %0, t; }" : "=r"(a) : "l"(p));
    return a;
}
#define CPA16(dst, src) \
    asm volatile("cp.async.cg.shared.global [%0], [%1], 16;" :: "r"(dst), "l"(src) : "memory")
#define CPA_COMMIT() asm volatile("cp.async.commit_group;" ::: "memory")
#define CPA_WAIT1()  asm volatile("cp.async.wait_group 1;" ::: "memory")
#define CPA_WAIT0()  asm volatile("cp.async.wait_group 0;" ::: "memory")

#define LDSM4(r0,r1,r2,r3, addr) \
    asm volatile("ldmatrix.sync.aligned.m8n8.x4.shared.b16 {%0,%1,%2,%3}, [%4];" \
                 : "=r"(r0), "=r"(r1), "=r"(r2), "=r"(r3) : "r"(addr))

#define MMA_F16(c0,c1,c2,c3, a0,a1,a2,a3, b0,b1) \
    asm volatile("mma.sync.aligned.m16n8k16.row.col.f32.f16.f16.f32 " \
                 "{%0,%1,%2,%3},{%4,%5,%6,%7},{%8,%9},{%0,%1,%2,%3};" \
                 : "+f"(c0), "+f"(c1), "+f"(c2), "+f"(c3) \
                 : "r"(a0), "r"(a1), "r"(a2), "r"(a3), "r"(b0), "r"(b1))

// ---------------------------------------------------------------------------
// fused fp32 -> fp16 conversion for hs, Wqkv, Wproj in one launch
// ---------------------------------------------------------------------------
#define N4_HS ((MTOT*KDIM)/4)
#define N4_WQ ((3*EMB*KDIM)/4)
#define N4_WP ((EMB*KDIM)/4)

__global__ __launch_bounds__(256)
void tohalf3_kernel(const float4* __restrict__ hs, const float4* __restrict__ wq,
                    const float4* __restrict__ wp,
                    uint2* __restrict__ hs_h, uint2* __restrict__ wq_h,
                    uint2* __restrict__ wp_h)
{
    int i = blockIdx.x * 256 + threadIdx.x;
    const float4* src;
    uint2* dst;
    int j;
    if (i < N4_HS)              { src = hs; dst = hs_h; j = i; }
    else if (i < N4_HS + N4_WQ) { src = wq; dst = wq_h; j = i - N4_HS; }
    else if (i < N4_HS + N4_WQ + N4_WP) { src = wp; dst = wp_h; j = i - N4_HS - N4_WQ; }
    else return;
    float4 v = src[j];
    __half2 h01 = __floats2half2_rn(v.x, v.y);
    __half2 h23 = __floats2half2_rn(v.z, v.w);
    uint2 ho;
    ho.x = *reinterpret_cast<uint32_t*>(&h01);
    ho.y = *reinterpret_cast<uint32_t*>(&h23);
    dst[j] = ho;
}

// ---------------------------------------------------------------------------
// mma.sync pure-fp16 GEMM: C[m][n] = sum_k A[m][k]*W[n][k] + bias[n]
// 128x128 CTA tile, 256 threads (8 warps as 2x4, warp tile 64x32).
// K chunk 32, cp.async double buffer (R7-proven structure), A hi-only.
// smem per buffer: Ah, Wh = 2 x 8KB = 16KB; x2 = 32KB.
// MODE 0: QKV scatter epilogue. MODE 1: plain fp32 store.
// ---------------------------------------------------------------------------
#define GEMM_DSMEM 32768

template<int MODE>
__global__ __launch_bounds__(256)
void mma_gemm(const __half* __restrict__ Ahi, const __half* __restrict__ Whi,
              const float* __restrict__ bias, const float* __restrict__ sscale,
              float* __restrict__ Cout)
{
    extern __shared__ __align__(128) char dsm[];
    __shared__ float s_bias[128];
    __shared__ float s_qs[16];

    const int tid  = threadIdx.x;
    const int lane = tid & 31;
    const int wid  = tid >> 5;
    const int wm   = wid >> 2;
    const int wn   = wid & 3;
    const int m0   = blockIdx.y * 128;
    const int n0   = blockIdx.x * 128;

    if (tid < 128) s_bias[tid] = bias[n0 + tid];
    if (MODE == 0 && tid < 16)
        s_qs[tid] = 0.125f * (1.0f + 0.01f * tanhf(sscale[tid]));

    const uint32_t sbase = smem_u32(dsm);

    const int lr  = tid >> 2;
    const int lc  = tid & 3;
    const uint32_t sw0 = (uint32_t)(lr * 64)        + ((lc ^ ((lr >> 1) & 3)) * 16);
    const uint32_t sw1 = (uint32_t)((lr + 64) * 64) + ((lc ^ (((lr + 64) >> 1) & 3)) * 16);

    const char* pAh0 = (const char*)Ahi + (size_t)(m0 + lr) * 2048 + lc * 16;
    const char* pWh0 = (const char*)Whi + (size_t)(n0 + lr) * 2048 + lc * 16;
    const size_t R64 = (size_t)64 * 2048;

    uint32_t aRow[4], aSwz[4];
#pragma unroll
    for (int mt = 0; mt < 4; ++mt) {
        int r = wm * 64 + mt * 16 + (lane & 15);
        aRow[mt] = r * 64;
        aSwz[mt] = (r >> 1) & 3;
    }
    const uint32_t aCsel = lane >> 4;
    uint32_t bRow[2], bSwz[2];
#pragma unroll
    for (int p = 0; p < 2; ++p) {
        int r = wn * 32 + p * 16 + ((lane >> 4) & 1) * 8 + (lane & 7);
        bRow[p] = r * 64;
        bSwz[p] = (r >> 1) & 3;
    }
    const uint32_t bCsel = (lane >> 3) & 1;

    float acc[4][4][4];
#pragma unroll
    for (int i = 0; i < 4; ++i)
#pragma unroll
        for (int j = 0; j < 4; ++j)
#pragma unroll
            for (int q = 0; q < 4; ++q) acc[i][j][q] = 0.f;

#define ISSUE(kc, buf) do {                                                   \
        uint32_t db = sbase + (buf) * 16384;                                  \
        size_t ko = (size_t)(kc) * 64;                                        \
        CPA16(db +         sw0, pAh0 + ko); CPA16(db +         sw1, pAh0 + R64 + ko); \
        CPA16(db + 8192 + sw0, pWh0 + ko); CPA16(db + 8192 + sw1, pWh0 + R64 + ko);  \
        CPA_COMMIT();                                                         \
    } while (0)

    ISSUE(0, 0);

    for (int kc = 0; kc < NKC; ++kc) {
        const int buf = kc & 1;
        if (kc + 1 < NKC) { ISSUE(kc + 1, buf ^ 1); CPA_WAIT1(); }
        else              { CPA_WAIT0(); }
        __syncthreads();

        const uint32_t db = sbase + buf * 16384;
#pragma unroll
        for (int ks = 0; ks < 2; ++ks) {
            uint32_t ah[4][4], bh[2][4];
            const uint32_t ac = (ks * 2 + aCsel);
            const uint32_t bc = (ks * 2 + bCsel);
#pragma unroll
            for (int mt = 0; mt < 4; ++mt) {
                uint32_t adA = db + aRow[mt] + ((ac ^ aSwz[mt]) * 16);
                LDSM4(ah[mt][0], ah[mt][1], ah[mt][2], ah[mt][3], adA);
            }
#pragma unroll
            for (int p = 0; p < 2; ++p) {
                uint32_t adB = db + 8192 + bRow[p] + ((bc ^ bSwz[p]) * 16);
                LDSM4(bh[p][0], bh[p][1], bh[p][2], bh[p][3], adB);
            }
#pragma unroll
            for (int mt = 0; mt < 4; ++mt)
#pragma unroll
                for (int nt = 0; nt < 4; ++nt) {
                    const int p = nt >> 1, o = (nt & 1) * 2;
                    MMA_F16(acc[mt][nt][0], acc[mt][nt][1], acc[mt][nt][2], acc[mt][nt][3],
                            ah[mt][0], ah[mt][1], ah[mt][2], ah[mt][3],
                            bh[p][o], bh[p][o + 1]);
                }
        }
        __syncthreads();
    }
#undef ISSUE

    // ---- epilogue ----
    const int tr = lane >> 2;
    const int tc = (lane & 3) * 2;
    if (MODE == 0) {
        const int part = n0 >> 10;       // 0:q 1:k 2:v (uniform per CTA)
        const int b = m0 >> 11;
#pragma unroll
        for (int mt = 0; mt < 4; ++mt) {
            const int t0 = (m0 & 2047) + wm * 64 + mt * 16 + tr;
#pragma unroll
            for (int nt = 0; nt < 4; ++nt) {
                const int colr = wn * 32 + nt * 8 + tc;
                const int e = (n0 & 1023) + colr;
                const int h = e >> 6;
                const int d = e & 63;
                const float b0 = s_bias[colr], b1 = s_bias[colr + 1];
                float v0 = acc[mt][nt][0] + b0, v1 = acc[mt][nt][1] + b1;
                float v2 = acc[mt][nt][2] + b0, v3 = acc[mt][nt][3] + b1;
                if (part <= 1) {
                    if (part == 0) {
                        const float qs = s_qs[h];
                        v0 *= qs; v1 *= qs; v2 *= qs; v3 *= qs;
                    }
                    __half* dstA = (part == 0) ? g_qh : g_kh;
                    __half2 h01 = __floats2half2_rn(v0, v1);
                    __half2 h23 = __floats2half2_rn(v2, v3);
                    size_t base = ((size_t)(b * NH + h) * SEQ + t0) * HD + d;
                    *(__half2*)&dstA[base] = h01;
                    *(__half2*)&dstA[base + 8 * HD] = h23;
                } else {
                    size_t base = ((size_t)(b * NH + h) * HD + d) * SEQ + t0;
                    g_vh[base]           = __float2half(v0);
                    g_vh[base + SEQ]     = __float2half(v1);
                    g_vh[base + 8]       = __float2half(v2);
                    g_vh[base + SEQ + 8] = __float2half(v3);
                }
            }
        }
    } else {
#pragma unroll
        for (int mt = 0; mt < 4; ++mt) {
            const int mg = m0 + wm * 64 + mt * 16 + tr;
#pragma unroll
            for (int nt = 0; nt < 4; ++nt) {
                const int colr = wn * 32 + nt * 8 + tc;
                const int ng = n0 + colr;
                const float b0 = s_bias[colr], b1 = s_bias[colr + 1];
                *(float2*)&Cout[(size_t)mg * EMB + ng] =
                    make_float2(acc[mt][nt][0] + b0, acc[mt][nt][1] + b1);
                *(float2*)&Cout[(size_t)(mg + 8) * EMB + ng] =
                    make_float2(acc[mt][nt][2] + b0, acc[mt][nt][3] + b1);
            }
        }
    }
}

// ---------------------------------------------------------------------------
// Tensor-core causal flash attention (pure fp16: Q,K,V,P hi-only).
// 64 q-rows per CTA, 4 warps x 16 rows; K/V tiles of 64, cp.async dbl-buffer
// (R7-proven structure). smem: buf{Kh,Vh} x2 (32KB) + Q (8KB) = 40KB.
// ---------------------------------------------------------------------------
#define ATT_DSMEM 40960

__global__ __launch_bounds__(128)
void attn_mma_kernel()
{
    extern __shared__ __align__(128) char dsm[];
    const int tid  = threadIdx.x;
    const int lane = tid & 31;
    const int wid  = tid >> 5;
    const int qt   = (int)gridDim.x - 1 - (int)blockIdx.x;  // long CTAs first
    const int bh   = blockIdx.y;

    const uint32_t sbase = smem_u32(dsm);
    const uint32_t qoff  = 32768;

    const int lrow = tid >> 3;           // 0..15
    const int lch  = tid & 7;            // 0..7
    uint32_t lso[4];
#pragma unroll
    for (int i = 0; i < 4; ++i) {
        int r = lrow + i * 16;
        lso[i] = (uint32_t)(r * 128 + ((lch ^ (r & 7)) * 16));
    }
    const __half* kh_g = g_kh + (size_t)bh * SEQ * HD;
    const __half* vh_g = g_vh + (size_t)bh * HD * SEQ;
    const __half* qh_g = g_qh + (size_t)bh * SEQ * HD;

#define AKV_ISSUE(ktile, buf) do {                                            \
        uint32_t db_ = sbase + (buf) * 16384;                                 \
        _Pragma("unroll")                                                     \
        for (int i_ = 0; i_ < 4; ++i_) {                                      \
            int r_ = lrow + i_ * 16;                                          \
            CPA16(db_ +         lso[i_], (const char*)(kh_g + ((size_t)((ktile)*64 + r_) * HD + lch * 8))); \
            CPA16(db_ + 8192 + lso[i_], (const char*)(vh_g + ((size_t)r_ * SEQ + (ktile)*64 + lch * 8))); \
        }                                                                     \
        CPA_COMMIT();                                                         \
    } while (0)

    // group 0: Q tile (hi only) + KV tile 0
    {
#pragma unroll
        for (int i = 0; i < 4; ++i) {
            int r = lrow + i * 16;
            CPA16(sbase + qoff + lso[i], (const char*)(qh_g + ((size_t)(qt*64 + r) * HD + lch * 8)));
        }
        AKV_ISSUE(0, 0);
    }

    const int ar  = wid * 16 + (lane & 15);
    const uint32_t aC = lane >> 4;
    const int rb  = ((lane >> 4) & 1) * 8 + (lane & 7);
    const uint32_t bCbit = (lane >> 3) & 1;

    float O[8][4];
#pragma unroll
    for (int j = 0; j < 8; ++j)
#pragma unroll
        for (int q = 0; q < 4; ++q) O[j][q] = 0.f;
    float m0 = -INFINITY, m1 = -INFINITY, l0 = 0.f, l1 = 0.f;

    for (int kt = 0; kt <= qt; ++kt) {
        const int buf = kt & 1;
        if (kt < qt) { AKV_ISSUE(kt + 1, buf ^ 1); CPA_WAIT1(); }
        else         { CPA_WAIT0(); }
        __syncthreads();

        const uint32_t db = sbase + buf * 16384;

        // ---- S = Q K^T (all hi) ----
        float S[8][4];
#pragma unroll
        for (int j = 0; j < 8; ++j)
#pragma unroll
            for (int q = 0; q < 4; ++q) S[j][q] = 0.f;

#pragma unroll
        for (int kk = 0; kk < 4; ++kk) {
            uint32_t qh0,qh1,qh2,qh3;
            uint32_t qaddr = sbase + qoff + ar * 128 + ((((uint32_t)(kk*2) + aC) ^ (ar & 7)) * 16);
            LDSM4(qh0, qh1, qh2, qh3, qaddr);
#pragma unroll
            for (int p = 0; p < 4; ++p) {
                int r = p * 16 + rb;
                uint32_t bc = (uint32_t)(kk * 2) + bCbit;
                uint32_t kaddr = db + r * 128 + ((bc ^ (r & 7)) * 16);
                uint32_t b0,b1,b2,b3;
                LDSM4(b0, b1, b2, b3, kaddr);
                MMA_F16(S[2*p][0],S[2*p][1],S[2*p][2],S[2*p][3],   qh0,qh1,qh2,qh3, b0,b1);
                MMA_F16(S[2*p+1][0],S[2*p+1][1],S[2*p+1][2],S[2*p+1][3], qh0,qh1,qh2,qh3, b2,b3);
            }
        }

        // ---- causal mask (diagonal tile only) ----
        if (kt == qt) {
            const int qr0 = wid * 16 + (lane >> 2);
            const int qr1 = qr0 + 8;
            const int cb  = (lane & 3) * 2;
#pragma unroll
            for (int j = 0; j < 8; ++j) {
                int c0c = j * 8 + cb;
                if (c0c     > qr0) S[j][0] = -1e30f;
                if (c0c + 1 > qr0) S[j][1] = -1e30f;
                if (c0c     > qr1) S[j][2] = -1e30f;
                if (c0c + 1 > qr1) S[j][3] = -1e30f;
            }
        }

        // ---- online softmax on fragments ----
        float mn0 = m0, mn1 = m1;
#pragma unroll
        for (int j = 0; j < 8; ++j) {
            mn0 = fmaxf(mn0, fmaxf(S[j][0], S[j][1]));
            mn1 = fmaxf(mn1, fmaxf(S[j][2], S[j][3]));
        }
        mn0 = fmaxf(mn0, __shfl_xor_sync(0xffffffffu, mn0, 1));
        mn0 = fmaxf(mn0, __shfl_xor_sync(0xffffffffu, mn0, 2));
        mn1 = fmaxf(mn1, __shfl_xor_sync(0xffffffffu, mn1, 1));
        mn1 = fmaxf(mn1, __shfl_xor_sync(0xffffffffu, mn1, 2));
        const float al0 = __expf(m0 - mn0);
        const float al1 = __expf(m1 - mn1);
        m0 = mn0; m1 = mn1;

        float ls0 = 0.f, ls1 = 0.f;
        uint32_t phi[4][4];
#pragma unroll
        for (int j = 0; j < 8; ++j) {
            float p0 = __expf(S[j][0] - mn0);
            float p1 = __expf(S[j][1] - mn0);
            float p2 = __expf(S[j][2] - mn1);
            float p3 = __expf(S[j][3] - mn1);
            ls0 += p0 + p1;
            ls1 += p2 + p3;
            __half2 h01 = __floats2half2_rn(p0, p1);
            __half2 h23 = __floats2half2_rn(p2, p3);
            const int kk = j >> 1, hh = (j & 1) * 2;
            phi[kk][hh]     = *reinterpret_cast<uint32_t*>(&h01);
            phi[kk][hh + 1] = *reinterpret_cast<uint32_t*>(&h23);
        }
        ls0 += __shfl_xor_sync(0xffffffffu, ls0, 1);
        ls0 += __shfl_xor_sync(0xffffffffu, ls0, 2);
        ls1 += __shfl_xor_sync(0xffffffffu, ls1, 1);
        ls1 += __shfl_xor_sync(0xffffffffu, ls1, 2);
        l0 = l0 * al0 + ls0;
        l1 = l1 * al1 + ls1;
#pragma unroll
        for (int j = 0; j < 8; ++j) {
            O[j][0] *= al0; O[j][1] *= al0;
            O[j][2] *= al1; O[j][3] *= al1;
        }

        // ---- O += P V (P hi; V hi) ----
#pragma unroll
        for (int kk = 0; kk < 4; ++kk) {
#pragma unroll
            for (int p = 0; p < 4; ++p) {
                int r = p * 16 + rb;
                uint32_t bc = (uint32_t)(kk * 2) + bCbit;
                uint32_t vaddr = db + 8192 + r * 128 + ((bc ^ (r & 7)) * 16);
                uint32_t v0,v1,v2,v3;
                LDSM4(v0, v1, v2, v3, vaddr);
                MMA_F16(O[2*p][0],O[2*p][1],O[2*p][2],O[2*p][3],
                        phi[kk][0],phi[kk][1],phi[kk][2],phi[kk][3], v0,v1);
                MMA_F16(O[2*p+1][0],O[2*p+1][1],O[2*p+1][2],O[2*p+1][3],
                        phi[kk][0],phi[kk][1],phi[kk][2],phi[kk][3], v2,v3);
            }
        }
        __syncthreads();
    }
#undef AKV_ISSUE

    // ---- epilogue: O / l -> fp16 att [b*T+t][e] (hi only) ----
    const float inv0 = 1.0f / l0;
    const float inv1 = 1.0f / l1;
    const int b = bh >> 4, h = bh & 15;
    const int tg0 = qt * 64 + wid * 16 + (lane >> 2);
    const size_t base0 = ((size_t)(b * SEQ + tg0)) * EMB + h * HD + (lane & 3) * 2;
    const size_t base1 = base0 + (size_t)8 * EMB;
#pragma unroll
    for (int j = 0; j < 8; ++j) {
        const int d = j * 8;
        __half2 h01 = __floats2half2_rn(O[j][0] * inv0, O[j][1] * inv0);
        __half2 h23 = __floats2half2_rn(O[j][2] * inv1, O[j][3] * inv1);
        *(uint32_t*)&g_att_hi[base0 + d] = *reinterpret_cast<uint32_t*>(&h01);
        *(uint32_t*)&g_att_hi[base1 + d] = *reinterpret_cast<uint32_t*>(&h23);
    }
}

// ---------------------------------------------------------------------------
extern "C" void kernel_launch(void* const* d_in, const int* in_sizes, int n_in,
                              void* d_out, int out_size)
{
    const float* hs    = (const float*)d_in[0];   // [4,2048,1024]
    const float* Wqkv  = (const float*)d_in[1];   // [3072,1024]
    const float* bqkv  = (const float*)d_in[2];   // [3072]
    const float* Wproj = (const float*)d_in[3];   // [1024,1024]
    const float* bproj = (const float*)d_in[4];   // [1024]
    const float* ss    = (const float*)d_in[5];   // [16]
    // d_in[6] = splat_bias: constant pre-softmax shift -> no-op in softmax
    float* out = (float*)d_out;

    void *hs_hi, *wq_hi, *wp_hi, *at_hi;
    cudaGetSymbolAddress(&hs_hi, g_hs_hi);
    cudaGetSymbolAddress(&wq_hi, g_wq_hi);
    cudaGetSymbolAddress(&wp_hi, g_wp_hi);
    cudaGetSymbolAddress(&at_hi, g_att_hi);

    cudaFuncSetAttribute(mma_gemm<0>, cudaFuncAttributeMaxDynamicSharedMemorySize, GEMM_DSMEM);
    cudaFuncSetAttribute(mma_gemm<1>, cudaFuncAttributeMaxDynamicSharedMemorySize, GEMM_DSMEM);
    cudaFuncSetAttribute(attn_mma_kernel, cudaFuncAttributeMaxDynamicSharedMemorySize, ATT_DSMEM);

    // 0) convert inputs/weights to fp16 in ONE fused launch
    const int n4_total = N4_HS + N4_WQ + N4_WP;
    tohalf3_kernel<<<(n4_total + 255) / 256, 256>>>(
        (const float4*)hs, (const float4*)Wqkv, (const float4*)Wproj,
        (uint2*)hs_hi, (uint2*)wq_hi, (uint2*)wp_hi);

    // 1) QKV projection (pure fp16) -> Q hi, K hi, V hi
    mma_gemm<0><<<dim3(3072/128, MTOT/128), 256, GEMM_DSMEM>>>(
        (const __half*)hs_hi, (const __half*)wq_hi, bqkv, ss, nullptr);

    // 2) causal flash attention (tensor cores, pure fp16, 64 q-rows/CTA)
    attn_mma_kernel<<<dim3(SEQ/64, BATCH*NH), 128, ATT_DSMEM>>>();

    // 3) output projection (pure fp16)
    mma_gemm<1><<<dim3(EMB/128, MTOT/128), 256, GEMM_DSMEM>>>(
        (const __half*)at_hi, (const __half*)wp_hi, bproj, nullptr, out);
}

// round 16
// speedup vs baseline: 1.5363x; 1.5363x over previous
#include <cuda_runtime.h>
#include <cuda_fp16.h>
#include <math.h>
#include <stdint.h>

#define BATCH 4
#define SEQ   2048
#define EMB   1024
#define NH    16
#define HD    64
#define MTOT  (BATCH*SEQ)   // 8192
#define KDIM  1024
#define KC    32            // GEMM K chunk
#define NKC   (KDIM/KC)     // 32 chunks

// ---------------- scratch (__device__ globals; allocation-free contract) ----
__device__ __half g_qh[(size_t)BATCH*NH*SEQ*HD];  // [bh][t][d], pre-scaled (hi only)
__device__ __half g_kh[(size_t)BATCH*NH*SEQ*HD];  // [bh][t][d]  (hi only)
__device__ __half g_vh[(size_t)BATCH*NH*HD*SEQ];  // [bh][d][t]  (hi only)
__device__ __half g_hs_hi[(size_t)MTOT*KDIM];
__device__ __half g_wq_hi[(size_t)3*EMB*KDIM];
__device__ __half g_wp_hi[(size_t)EMB*KDIM];
__device__ __half g_att_hi[(size_t)MTOT*EMB];

// ---------------- PTX helpers (baseline ISA only: sm_80-era) ----------------
__device__ __forceinline__ uint32_t smem_u32(const void* p) {
    uint32_t a;
    asm("{ .reg .u64 t; cvta.to.shared.u64 t, %1; cvt.u32.u64 %0, t; }" : "=r"(a) : "l"(p));
    return a;
}
#define CPA16(dst, src) \
    asm volatile("cp.async.cg.shared.global [%0], [%1], 16;" :: "r"(dst), "l"(src) : "memory")
#define CPA_COMMIT() asm volatile("cp.async.commit_group;" ::: "memory")
#define CPA_WAIT1()  asm volatile("cp.async.wait_group 1;" ::: "memory")
#define CPA_WAIT0()  asm volatile("cp.async.wait_group 0;" ::: "memory")

#define LDSM4(r0,r1,r2,r3, addr) \
    asm volatile("ldmatrix.sync.aligned.m8n8.x4.shared.b16 {%0,%1,%2,%3}, [%4];" \
                 : "=r"(r0), "=r"(r1), "=r"(r2), "=r"(r3) : "r"(addr))

#define MMA_F16(c0,c1,c2,c3, a0,a1,a2,a3, b0,b1) \
    asm volatile("mma.sync.aligned.m16n8k16.row.col.f32.f16.f16.f32 " \
                 "{%0,%1,%2,%3},{%4,%5,%6,%7},{%8,%9},{%0,%1,%2,%3};" \
                 : "+f"(c0), "+f"(c1), "+f"(c2), "+f"(c3) \
                 : "r"(a0), "r"(a1), "r"(a2), "r"(a3), "r"(b0), "r"(b1))

// ---------------------------------------------------------------------------
// fused fp32 -> fp16 conversion for hs, Wqkv, Wproj in one launch
// ---------------------------------------------------------------------------
#define N4_HS ((MTOT*KDIM)/4)
#define N4_WQ ((3*EMB*KDIM)/4)
#define N4_WP ((EMB*KDIM)/4)

__global__ __launch_bounds__(256)
void tohalf3_kernel(const float4* __restrict__ hs, const float4* __restrict__ wq,
                    const float4* __restrict__ wp,
                    uint2* __restrict__ hs_h, uint2* __restrict__ wq_h,
                    uint2* __restrict__ wp_h)
{
    int i = blockIdx.x * 256 + threadIdx.x;
    const float4* src;
    uint2* dst;
    int j;
    if (i < N4_HS)              { src = hs; dst = hs_h; j = i; }
    else if (i < N4_HS + N4_WQ) { src = wq; dst = wq_h; j = i - N4_HS; }
    else if (i < N4_HS + N4_WQ + N4_WP) { src = wp; dst = wp_h; j = i - N4_HS - N4_WQ; }
    else return;
    float4 v = src[j];
    __half2 h01 = __floats2half2_rn(v.x, v.y);
    __half2 h23 = __floats2half2_rn(v.z, v.w);
    uint2 ho;
    ho.x = *reinterpret_cast<uint32_t*>(&h01);
    ho.y = *reinterpret_cast<uint32_t*>(&h23);
    dst[j] = ho;
}

// ---------------------------------------------------------------------------
// mma.sync pure-fp16 GEMM: C[m][n] = sum_k A[m][k]*W[n][k] + bias[n]
// 128x128 CTA tile, 256 threads (8 warps as 2x4, warp tile 64x32).
// K chunk 32, cp.async double buffer (R7-proven structure), A hi-only.
// smem per buffer: Ah, Wh = 2 x 8KB = 16KB; x2 = 32KB.
// MODE 0: QKV scatter epilogue. MODE 1: plain fp32 store.
// ---------------------------------------------------------------------------
#define GEMM_DSMEM 32768

template<int MODE>
__global__ __launch_bounds__(256)
void mma_gemm(const __half* __restrict__ Ahi, const __half* __restrict__ Whi,
              const float* __restrict__ bias, const float* __restrict__ sscale,
              float* __restrict__ Cout)
{
    extern __shared__ __align__(128) char dsm[];
    __shared__ float s_bias[128];
    __shared__ float s_qs[16];

    const int tid  = threadIdx.x;
    const int lane = tid & 31;
    const int wid  = tid >> 5;
    const int wm   = wid >> 2;
    const int wn   = wid & 3;
    const int m0   = blockIdx.y * 128;
    const int n0   = blockIdx.x * 128;

    if (tid < 128) s_bias[tid] = bias[n0 + tid];
    if (MODE == 0 && tid < 16)
        s_qs[tid] = 0.125f * (1.0f + 0.01f * tanhf(sscale[tid]));

    const uint32_t sbase = smem_u32(dsm);

    const int lr  = tid >> 2;
    const int lc  = tid & 3;
    const uint32_t sw0 = (uint32_t)(lr * 64)        + ((lc ^ ((lr >> 1) & 3)) * 16);
    const uint32_t sw1 = (uint32_t)((lr + 64) * 64) + ((lc ^ (((lr + 64) >> 1) & 3)) * 16);

    const char* pAh0 = (const char*)Ahi + (size_t)(m0 + lr) * 2048 + lc * 16;
    const char* pWh0 = (const char*)Whi + (size_t)(n0 + lr) * 2048 + lc * 16;
    const size_t R64 = (size_t)64 * 2048;

    uint32_t aRow[4], aSwz[4];
#pragma unroll
    for (int mt = 0; mt < 4; ++mt) {
        int r = wm * 64 + mt * 16 + (lane & 15);
        aRow[mt] = r * 64;
        aSwz[mt] = (r >> 1) & 3;
    }
    const uint32_t aCsel = lane >> 4;
    uint32_t bRow[2], bSwz[2];
#pragma unroll
    for (int p = 0; p < 2; ++p) {
        int r = wn * 32 + p * 16 + ((lane >> 4) & 1) * 8 + (lane & 7);
        bRow[p] = r * 64;
        bSwz[p] = (r >> 1) & 3;
    }
    const uint32_t bCsel = (lane >> 3) & 1;

    float acc[4][4][4];
#pragma unroll
    for (int i = 0; i < 4; ++i)
#pragma unroll
        for (int j = 0; j < 4; ++j)
#pragma unroll
            for (int q = 0; q < 4; ++q) acc[i][j][q] = 0.f;

#define ISSUE(kc, buf) do {                                                   \
        uint32_t db = sbase + (buf) * 16384;                                  \
        size_t ko = (size_t)(kc) * 64;                                        \
        CPA16(db +         sw0, pAh0 + ko); CPA16(db +         sw1, pAh0 + R64 + ko); \
        CPA16(db + 8192 + sw0, pWh0 + ko); CPA16(db + 8192 + sw1, pWh0 + R64 + ko);  \
        CPA_COMMIT();                                                         \
    } while (0)

    ISSUE(0, 0);

    for (int kc = 0; kc < NKC; ++kc) {
        const int buf = kc & 1;
        if (kc + 1 < NKC) { ISSUE(kc + 1, buf ^ 1); CPA_WAIT1(); }
        else              { CPA_WAIT0(); }
        __syncthreads();

        const uint32_t db = sbase + buf * 16384;
#pragma unroll
        for (int ks = 0; ks < 2; ++ks) {
            uint32_t ah[4][4], bh[2][4];
            const uint32_t ac = (ks * 2 + aCsel);
            const uint32_t bc = (ks * 2 + bCsel);
#pragma unroll
            for (int mt = 0; mt < 4; ++mt) {
                uint32_t adA = db + aRow[mt] + ((ac ^ aSwz[mt]) * 16);
                LDSM4(ah[mt][0], ah[mt][1], ah[mt][2], ah[mt][3], adA);
            }
#pragma unroll
            for (int p = 0; p < 2; ++p) {
                uint32_t adB = db + 8192 + bRow[p] + ((bc ^ bSwz[p]) * 16);
                LDSM4(bh[p][0], bh[p][1], bh[p][2], bh[p][3], adB);
            }
#pragma unroll
            for (int mt = 0; mt < 4; ++mt)
#pragma unroll
                for (int nt = 0; nt < 4; ++nt) {
                    const int p = nt >> 1, o = (nt & 1) * 2;
                    MMA_F16(acc[mt][nt][0], acc[mt][nt][1], acc[mt][nt][2], acc[mt][nt][3],
                            ah[mt][0], ah[mt][1], ah[mt][2], ah[mt][3],
                            bh[p][o], bh[p][o + 1]);
                }
        }
        __syncthreads();
    }
#undef ISSUE

    // ---- epilogue ----
    const int tr = lane >> 2;
    const int tc = (lane & 3) * 2;
    if (MODE == 0) {
        const int part = n0 >> 10;       // 0:q 1:k 2:v (uniform per CTA)
        const int b = m0 >> 11;
#pragma unroll
        for (int mt = 0; mt < 4; ++mt) {
            const int t0 = (m0 & 2047) + wm * 64 + mt * 16 + tr;
#pragma unroll
            for (int nt = 0; nt < 4; ++nt) {
                const int colr = wn * 32 + nt * 8 + tc;
                const int e = (n0 & 1023) + colr;
                const int h = e >> 6;
                const int d = e & 63;
                const float b0 = s_bias[colr], b1 = s_bias[colr + 1];
                float v0 = acc[mt][nt][0] + b0, v1 = acc[mt][nt][1] + b1;
                float v2 = acc[mt][nt][2] + b0, v3 = acc[mt][nt][3] + b1;
                if (part <= 1) {
                    if (part == 0) {
                        const float qs = s_qs[h];
                        v0 *= qs; v1 *= qs; v2 *= qs; v3 *= qs;
                    }
                    __half* dstA = (part == 0) ? g_qh : g_kh;
                    __half2 h01 = __floats2half2_rn(v0, v1);
                    __half2 h23 = __floats2half2_rn(v2, v3);
                    size_t base = ((size_t)(b * NH + h) * SEQ + t0) * HD + d;
                    *(__half2*)&dstA[base] = h01;
                    *(__half2*)&dstA[base + 8 * HD] = h23;
                } else {
                    size_t base = ((size_t)(b * NH + h) * HD + d) * SEQ + t0;
                    g_vh[base]           = __float2half(v0);
                    g_vh[base + SEQ]     = __float2half(v1);
                    g_vh[base + 8]       = __float2half(v2);
                    g_vh[base + SEQ + 8] = __float2half(v3);
                }
            }
        }
    } else {
#pragma unroll
        for (int mt = 0; mt < 4; ++mt) {
            const int mg = m0 + wm * 64 + mt * 16 + tr;
#pragma unroll
            for (int nt = 0; nt < 4; ++nt) {
                const int colr = wn * 32 + nt * 8 + tc;
                const int ng = n0 + colr;
                const float b0 = s_bias[colr], b1 = s_bias[colr + 1];
                *(float2*)&Cout[(size_t)mg * EMB + ng] =
                    make_float2(acc[mt][nt][0] + b0, acc[mt][nt][1] + b1);
                *(float2*)&Cout[(size_t)(mg + 8) * EMB + ng] =
                    make_float2(acc[mt][nt][2] + b0, acc[mt][nt][3] + b1);
            }
        }
    }
}

// ---------------------------------------------------------------------------
// Tensor-core causal flash attention (pure fp16: Q,K,V,P hi-only).
// 64 q-rows per CTA, 4 warps x 16 rows; K/V tiles of 64, cp.async dbl-buffer
// (R7-proven structure). smem: buf{Kh,Vh} x2 (32KB) + Q (8KB) = 40KB.
// ---------------------------------------------------------------------------
#define ATT_DSMEM 40960

__global__ __launch_bounds__(128)
void attn_mma_kernel()
{
    extern __shared__ __align__(128) char dsm[];
    const int tid  = threadIdx.x;
    const int lane = tid & 31;
    const int wid  = tid >> 5;
    const int qt   = (int)gridDim.x - 1 - (int)blockIdx.x;  // long CTAs first
    const int bh   = blockIdx.y;

    const uint32_t sbase = smem_u32(dsm);
    const uint32_t qoff  = 32768;

    const int lrow = tid >> 3;           // 0..15
    const int lch  = tid & 7;            // 0..7
    uint32_t lso[4];
#pragma unroll
    for (int i = 0; i < 4; ++i) {
        int r = lrow + i * 16;
        lso[i] = (uint32_t)(r * 128 + ((lch ^ (r & 7)) * 16));
    }
    const __half* kh_g = g_kh + (size_t)bh * SEQ * HD;
    const __half* vh_g = g_vh + (size_t)bh * HD * SEQ;
    const __half* qh_g = g_qh + (size_t)bh * SEQ * HD;

#define AKV_ISSUE(ktile, buf) do {                                            \
        uint32_t db_ = sbase + (buf) * 16384;                                 \
        _Pragma("unroll")                                                     \
        for (int i_ = 0; i_ < 4; ++i_) {                                      \
            int r_ = lrow + i_ * 16;                                          \
            CPA16(db_ +         lso[i_], (const char*)(kh_g + ((size_t)((ktile)*64 + r_) * HD + lch * 8))); \
            CPA16(db_ + 8192 + lso[i_], (const char*)(vh_g + ((size_t)r_ * SEQ + (ktile)*64 + lch * 8))); \
        }                                                                     \
        CPA_COMMIT();                                                         \
    } while (0)

    // group 0: Q tile (hi only) + KV tile 0
    {
#pragma unroll
        for (int i = 0; i < 4; ++i) {
            int r = lrow + i * 16;
            CPA16(sbase + qoff + lso[i], (const char*)(qh_g + ((size_t)(qt*64 + r) * HD + lch * 8)));
        }
        AKV_ISSUE(0, 0);
    }

    const int ar  = wid * 16 + (lane & 15);
    const uint32_t aC = lane >> 4;
    const int rb  = ((lane >> 4) & 1) * 8 + (lane & 7);
    const uint32_t bCbit = (lane >> 3) & 1;

    float O[8][4];
#pragma unroll
    for (int j = 0; j < 8; ++j)
#pragma unroll
        for (int q = 0; q < 4; ++q) O[j][q] = 0.f;
    float m0 = -INFINITY, m1 = -INFINITY, l0 = 0.f, l1 = 0.f;

    for (int kt = 0; kt <= qt; ++kt) {
        const int buf = kt & 1;
        if (kt < qt) { AKV_ISSUE(kt + 1, buf ^ 1); CPA_WAIT1(); }
        else         { CPA_WAIT0(); }
        __syncthreads();

        const uint32_t db = sbase + buf * 16384;

        // ---- S = Q K^T (all hi) ----
        float S[8][4];
#pragma unroll
        for (int j = 0; j < 8; ++j)
#pragma unroll
            for (int q = 0; q < 4; ++q) S[j][q] = 0.f;

#pragma unroll
        for (int kk = 0; kk < 4; ++kk) {
            uint32_t qh0,qh1,qh2,qh3;
            uint32_t qaddr = sbase + qoff + ar * 128 + ((((uint32_t)(kk*2) + aC) ^ (ar & 7)) * 16);
            LDSM4(qh0, qh1, qh2, qh3, qaddr);
#pragma unroll
            for (int p = 0; p < 4; ++p) {
                int r = p * 16 + rb;
                uint32_t bc = (uint32_t)(kk * 2) + bCbit;
                uint32_t kaddr = db + r * 128 + ((bc ^ (r & 7)) * 16);
                uint32_t b0,b1,b2,b3;
                LDSM4(b0, b1, b2, b3, kaddr);
                MMA_F16(S[2*p][0],S[2*p][1],S[2*p][2],S[2*p][3],   qh0,qh1,qh2,qh3, b0,b1);
                MMA_F16(S[2*p+1][0],S[2*p+1][1],S[2*p+1][2],S[2*p+1][3], qh0,qh1,qh2,qh3, b2,b3);
            }
        }

        // ---- causal mask (diagonal tile only) ----
        if (kt == qt) {
            const int qr0 = wid * 16 + (lane >> 2);
            const int qr1 = qr0 + 8;
            const int cb  = (lane & 3) * 2;
#pragma unroll
            for (int j = 0; j < 8; ++j) {
                int c0c = j * 8 + cb;
                if (c0c     > qr0) S[j][0] = -1e30f;
                if (c0c + 1 > qr0) S[j][1] = -1e30f;
                if (c0c     > qr1) S[j][2] = -1e30f;
                if (c0c + 1 > qr1) S[j][3] = -1e30f;
            }
        }

        // ---- online softmax on fragments ----
        float mn0 = m0, mn1 = m1;
#pragma unroll
        for (int j = 0; j < 8; ++j) {
            mn0 = fmaxf(mn0, fmaxf(S[j][0], S[j][1]));
            mn1 = fmaxf(mn1, fmaxf(S[j][2], S[j][3]));
        }
        mn0 = fmaxf(mn0, __shfl_xor_sync(0xffffffffu, mn0, 1));
        mn0 = fmaxf(mn0, __shfl_xor_sync(0xffffffffu, mn0, 2));
        mn1 = fmaxf(mn1, __shfl_xor_sync(0xffffffffu, mn1, 1));
        mn1 = fmaxf(mn1, __shfl_xor_sync(0xffffffffu, mn1, 2));
        const float al0 = __expf(m0 - mn0);
        const float al1 = __expf(m1 - mn1);
        m0 = mn0; m1 = mn1;

        float ls0 = 0.f, ls1 = 0.f;
        uint32_t phi[4][4];
#pragma unroll
        for (int j = 0; j < 8; ++j) {
            float p0 = __expf(S[j][0] - mn0);
            float p1 = __expf(S[j][1] - mn0);
            float p2 = __expf(S[j][2] - mn1);
            float p3 = __expf(S[j][3] - mn1);
            ls0 += p0 + p1;
            ls1 += p2 + p3;
            __half2 h01 = __floats2half2_rn(p0, p1);
            __half2 h23 = __floats2half2_rn(p2, p3);
            const int kk = j >> 1, hh = (j & 1) * 2;
            phi[kk][hh]     = *reinterpret_cast<uint32_t*>(&h01);
            phi[kk][hh + 1] = *reinterpret_cast<uint32_t*>(&h23);
        }
        ls0 += __shfl_xor_sync(0xffffffffu, ls0, 1);
        ls0 += __shfl_xor_sync(0xffffffffu, ls0, 2);
        ls1 += __shfl_xor_sync(0xffffffffu, ls1, 1);
        ls1 += __shfl_xor_sync(0xffffffffu, ls1, 2);
        l0 = l0 * al0 + ls0;
        l1 = l1 * al1 + ls1;
#pragma unroll
        for (int j = 0; j < 8; ++j) {
            O[j][0] *= al0; O[j][1] *= al0;
            O[j][2] *= al1; O[j][3] *= al1;
        }

        // ---- O += P V (P hi; V hi) ----
#pragma unroll
        for (int kk = 0; kk < 4; ++kk) {
#pragma unroll
            for (int p = 0; p < 4; ++p) {
                int r = p * 16 + rb;
                uint32_t bc = (uint32_t)(kk * 2) + bCbit;
                uint32_t vaddr = db + 8192 + r * 128 + ((bc ^ (r & 7)) * 16);
                uint32_t v0,v1,v2,v3;
                LDSM4(v0, v1, v2, v3, vaddr);
                MMA_F16(O[2*p][0],O[2*p][1],O[2*p][2],O[2*p][3],
                        phi[kk][0],phi[kk][1],phi[kk][2],phi[kk][3], v0,v1);
                MMA_F16(O[2*p+1][0],O[2*p+1][1],O[2*p+1][2],O[2*p+1][3],
                        phi[kk][0],phi[kk][1],phi[kk][2],phi[kk][3], v2,v3);
            }
        }
        __syncthreads();
    }
#undef AKV_ISSUE

    // ---- epilogue: O / l -> fp16 att [b*T+t][e] (hi only) ----
    const float inv0 = 1.0f / l0;
    const float inv1 = 1.0f / l1;
    const int b = bh >> 4, h = bh & 15;
    const int tg0 = qt * 64 + wid * 16 + (lane >> 2);
    const size_t base0 = ((size_t)(b * SEQ + tg0)) * EMB + h * HD + (lane & 3) * 2;
    const size_t base1 = base0 + (size_t)8 * EMB;
#pragma unroll
    for (int j = 0; j < 8; ++j) {
        const int d = j * 8;
        __half2 h01 = __floats2half2_rn(O[j][0] * inv0, O[j][1] * inv0);
        __half2 h23 = __floats2half2_rn(O[j][2] * inv1, O[j][3] * inv1);
        *(uint32_t*)&g_att_hi[base0 + d] = *reinterpret_cast<uint32_t*>(&h01);
        *(uint32_t*)&g_att_hi[base1 + d] = *reinterpret_cast<uint32_t*>(&h23);
    }
}

// ---------------------------------------------------------------------------
extern "C" void kernel_launch(void* const* d_in, const int* in_sizes, int n_in,
                              void* d_out, int out_size)
{
    const float* hs    = (const float*)d_in[0];   // [4,2048,1024]
    const float* Wqkv  = (const float*)d_in[1];   // [3072,1024]
    const float* bqkv  = (const float*)d_in[2];   // [3072]
    const float* Wproj = (const float*)d_in[3];   // [1024,1024]
    const float* bproj = (const float*)d_in[4];   // [1024]
    const float* ss    = (const float*)d_in[5];   // [16]
    // d_in[6] = splat_bias: constant pre-softmax shift -> no-op in softmax
    float* out = (float*)d_out;

    void *hs_hi, *wq_hi, *wp_hi, *at_hi;
    cudaGetSymbolAddress(&hs_hi, g_hs_hi);
    cudaGetSymbolAddress(&wq_hi, g_wq_hi);
    cudaGetSymbolAddress(&wp_hi, g_wp_hi);
    cudaGetSymbolAddress(&at_hi, g_att_hi);

    cudaFuncSetAttribute(mma_gemm<0>, cudaFuncAttributeMaxDynamicSharedMemorySize, GEMM_DSMEM);
    cudaFuncSetAttribute(mma_gemm<1>, cudaFuncAttributeMaxDynamicSharedMemorySize, GEMM_DSMEM);
    cudaFuncSetAttribute(attn_mma_kernel, cudaFuncAttributeMaxDynamicSharedMemorySize, ATT_DSMEM);

    // 0) convert inputs/weights to fp16 in ONE fused launch
    const int n4_total = N4_HS + N4_WQ + N4_WP;
    tohalf3_kernel<<<(n4_total + 255) / 256, 256>>>(
        (const float4*)hs, (const float4*)Wqkv, (const float4*)Wproj,
        (uint2*)hs_hi, (uint2*)wq_hi, (uint2*)wp_hi);

    // 1) QKV projection (pure fp16) -> Q hi, K hi, V hi
    mma_gemm<0><<<dim3(3072/128, MTOT/128), 256, GEMM_DSMEM>>>(
        (const __half*)hs_hi, (const __half*)wq_hi, bqkv, ss, nullptr);

    // 2) causal flash attention (tensor cores, pure fp16, 64 q-rows/CTA)
    attn_mma_kernel<<<dim3(SEQ/64, BATCH*NH), 128, ATT_DSMEM>>>();

    // 3) output projection (pure fp16)
    mma_gemm<1><<<dim3(EMB/128, MTOT/128), 256, GEMM_DSMEM>>>(
        (const __half*)at_hi, (const __half*)wp_hi, bproj, nullptr, out);
}